// round 17
// baseline (speedup 1.0000x reference)
#include <cuda_runtime.h>
#include <cstdint>

#define NB 128
#define NV 128000
#define KTOP 20
#define CHUNKS 8
#define TVEC 4000           // vec4 per chunk (16000 elems)
#define ABLK 512
#define CAPL 512            // per-chunk shared candidate cap (mean ~22, >100 sigma)
#define CAPG 1024
#define THRESH 3.0f

__device__ unsigned long long g_cand[NB][CAPG];
__device__ unsigned long long g_gkey[NB];
__device__ int   g_cnt[NB];
__device__ int   g_done[NB];
__device__ float g_sums[NB][CHUNKS];

__device__ __forceinline__ float fast_ex2(float x) {
    float r; asm("ex2.approx.ftz.f32 %0, %1;" : "=f"(r) : "f"(x)); return r;
}
__device__ __forceinline__ float fast_lg2(float x) {
    float r; asm("lg2.approx.ftz.f32 %0, %1;" : "=f"(r) : "f"(x)); return r;
}

// Streaming vec4 load pinned in SASS order (asm volatile).
__device__ __forceinline__ float4 ldg_cs4(const float4* p) {
    float4 v;
    asm volatile("ld.global.cs.v4.f32 {%0,%1,%2,%3}, [%4];"
                 : "=f"(v.x), "=f"(v.y), "=f"(v.z), "=f"(v.w) : "l"(p));
    return v;
}

// Monotone pack: larger value wins; on equal value, SMALLER index wins (jax tie rule).
__device__ __forceinline__ unsigned long long packkey(float v, int idx) {
    unsigned fb = __float_as_uint(v);
    fb = (fb & 0x80000000u) ? ~fb : (fb | 0x80000000u);
    return ((unsigned long long)fb << 32) | (unsigned long long)(~(unsigned)idx);
}

// Accurate -ln(u) for u in (0,1): poly(log1p) near 1, MUFU lg2 elsewhere.
__device__ __forceinline__ float neg_log(float u) {
    float d = u - 1.0f;
    float p = fmaf(d, 0.2f, -0.25f);
    p = fmaf(d, p, 0.333333333f);
    p = fmaf(d, p, -0.5f);
    p = fmaf(d, p, 1.0f);
    float lp = -d * p;                        // -log1p(d), good for d in (-0.16, 0]
    float lm = -0.693147181f * fast_lg2(u);
    return (u > 0.84f) ? lp : lm;
}

__global__ __launch_bounds__(ABLK) void sampler_kernel(
    const float* __restrict__ logits,
    const float* __restrict__ temp,
    const float* __restrict__ u,
    float* __restrict__ out)
{
    const int t     = blockIdx.x;
    const int row   = t >> 3;
    const int chunk = t & 7;
    const int tid   = threadIdx.x;

    // s_keys doubles as: scan-phase local candidate buffer (CAPL) and
    // combine-phase full-row key buffer (CAPG).
    __shared__ unsigned long long s_keys[CAPG + 4];
    __shared__ unsigned long long s_best;
    __shared__ unsigned long long s_sel[KTOP];
    __shared__ unsigned long long s_win;
    __shared__ float s_warp[ABLK / 32];
    __shared__ float s_lse;
    __shared__ int   s_lcnt;
    __shared__ int   s_base;
    __shared__ int   s_last;

    if (tid == 0) { s_best = 0ull; s_lcnt = 0; }
    __syncthreads();

    const float tv    = temp[row];
    const bool greedy = (tv < 1e-5f);
    const float tt    = greedy ? 1.0f : tv;
    const float inv_t = 1.0f / tt;
    const float c     = inv_t * 1.44269504088896f;

    const float4* __restrict__ lg4 = (const float4*)(logits + (size_t)row * NV) + chunk * TVEC;
    const float4* __restrict__ u4  = (const float4*)(u      + (size_t)row * NV) + chunk * TVEC;
    const int ebase = 4 * chunk * TVEC;

    float acc0 = 0.0f, acc1 = 0.0f;
    float best_e  = 0.0f;
    float best_lq = 1.0f;
    int   best_gi = 0;
    float invK    = 1e30f;

    // SHARED-memory candidate append (the fix: no global atomics in hot loop).
    #define RARE(lv, uv, ee, gidx)                                                  \
    {                                                                               \
        if ((lv) > THRESH) {                                                        \
            int p = atomicAdd(&s_lcnt, 1);                                          \
            if (p < CAPL) s_keys[p] = packkey((lv), (gidx));                        \
        }                                                                           \
        if (fmaf((ee), invK, (uv)) > 0.999f) {                                      \
            float lq = neg_log(uv);                                                 \
            if ((ee) * best_lq > best_e * lq) {                                     \
                best_e = (ee); best_lq = lq; best_gi = (gidx);                      \
                invK = 1.01f * (lq / (ee));                                         \
            }                                                                       \
        }                                                                           \
    }
    #define ELEM(lv, uv, ee, gidx)                                                  \
    {                                                                               \
        bool hot = ((lv) > THRESH) | (fmaf((ee), invK, (uv)) > 0.999f);             \
        if (hot) RARE(lv, uv, ee, gidx)                                             \
    }
    #define PROC(L, U, goff)                                                        \
    {                                                                               \
        float e0 = fast_ex2(L.x * c), e1 = fast_ex2(L.y * c);                       \
        float e2 = fast_ex2(L.z * c), e3 = fast_ex2(L.w * c);                       \
        acc0 += (e0 + e1); acc1 += (e2 + e3);                                       \
        ELEM(L.x, U.x, e0, (goff) + 0) ELEM(L.y, U.y, e1, (goff) + 1)               \
        ELEM(L.z, U.z, e2, (goff) + 2) ELEM(L.w, U.w, e3, (goff) + 3)               \
    }
    #define GELEM(lv, gidx)                                                         \
    {                                                                               \
        if ((lv) > THRESH) {                                                        \
            int p = atomicAdd(&s_lcnt, 1);                                          \
            if (p < CAPL) s_keys[p] = packkey((lv), (gidx));                        \
        }                                                                           \
    }
    #define GPROC(L, goff)                                                          \
    {                                                                               \
        float e0 = fast_ex2(L.x * c), e1 = fast_ex2(L.y * c);                       \
        float e2 = fast_ex2(L.z * c), e3 = fast_ex2(L.w * c);                       \
        acc0 += (e0 + e1); acc1 += (e2 + e3);                                       \
        GELEM(L.x, (goff) + 0) GELEM(L.y, (goff) + 1)                               \
        GELEM(L.z, (goff) + 2) GELEM(L.w, (goff) + 3)                               \
    }

    // R9/R16-proven 3-deep pinned loop; remainder boundaries land on warp
    // multiples (416 = 13*32), so all guards are warp-uniform.
    if (greedy) {
        int i = tid;
        for (; i + 2 * ABLK < TVEC; i += 3 * ABLK) {
            float4 L0 = ldg_cs4(lg4 + i);
            float4 L1 = ldg_cs4(lg4 + i + ABLK);
            float4 L2 = ldg_cs4(lg4 + i + 2 * ABLK);
            GPROC(L0, ebase + 4 * i)
            GPROC(L1, ebase + 4 * (i + ABLK))
            GPROC(L2, ebase + 4 * (i + 2 * ABLK))
        }
        for (; i < TVEC; i += ABLK) {
            float4 L0 = ldg_cs4(lg4 + i);
            GPROC(L0, ebase + 4 * i)
        }
    } else {
        int i = tid;
        for (; i + 2 * ABLK < TVEC; i += 3 * ABLK) {
            float4 L0 = ldg_cs4(lg4 + i);
            float4 U0 = ldg_cs4(u4  + i);
            float4 L1 = ldg_cs4(lg4 + i + ABLK);
            float4 U1 = ldg_cs4(u4  + i + ABLK);
            float4 L2 = ldg_cs4(lg4 + i + 2 * ABLK);
            float4 U2 = ldg_cs4(u4  + i + 2 * ABLK);
            PROC(L0, U0, ebase + 4 * i)
            PROC(L1, U1, ebase + 4 * (i + ABLK))
            PROC(L2, U2, ebase + 4 * (i + 2 * ABLK))
        }
        for (; i < TVEC; i += ABLK) {
            float4 L0 = ldg_cs4(lg4 + i);
            float4 U0 = ldg_cs4(u4  + i);
            PROC(L0, U0, ebase + 4 * i)
        }
    }
    #undef GPROC
    #undef GELEM
    #undef PROC
    #undef ELEM
    #undef RARE

    // ---- per-chunk reductions ----
    float sumexp = acc0 + acc1;
    #pragma unroll
    for (int o = 16; o; o >>= 1) sumexp += __shfl_down_sync(0xFFFFFFFFu, sumexp, o);
    if ((tid & 31) == 0) s_warp[tid >> 5] = sumexp;
    atomicMax(&s_best, packkey(best_e / best_lq, best_gi));
    __syncthreads();

    // bulk flush: one global atomic per CTA + coalesced candidate copy
    const int lcnt = min(s_lcnt, CAPL);
    if (tid == 0) {
        float s = 0.0f;
        #pragma unroll
        for (int w = 0; w < ABLK / 32; w++) s += s_warp[w];
        g_sums[row][chunk] = s;                       // fixed slot -> deterministic re-sum
        atomicMax(&g_gkey[row], s_best);              // commutative
        s_base = atomicAdd(&g_cnt[row], lcnt);
    }
    __syncthreads();
    {
        const int base = s_base;
        for (int p = tid; p < lcnt; p += ABLK)
            if (base + p < CAPG) g_cand[row][base + p] = s_keys[p];
    }

    // ---- last-CTA-per-row handoff ----
    __threadfence();
    __syncthreads();
    if (tid == 0) s_last = (atomicAdd(&g_done[row], 1) == CHUNKS - 1) ? 1 : 0;
    __syncthreads();
    if (!s_last) return;

    // =========== combine: only the last CTA of this row ===========
    const int cnt = *(volatile int*)&g_cnt[row];
    if (tid == 0) {
        float s = 0.0f;
        #pragma unroll
        for (int c2 = 0; c2 < CHUNKS; c2++) s += g_sums[row][c2];
        s_lse = 0.693147181f * fast_lg2(s);
    }

    const bool ok = (cnt >= KTOP) && (cnt <= CAPG);
    if (ok) {
        const int cnt4 = (cnt + 3) & ~3;
        for (int p = tid; p < cnt4; p += ABLK)
            s_keys[p] = (p < cnt) ? g_cand[row][p] : 0ull;   // 0 = smallest key
        __syncthreads();
        for (int p = tid; p < cnt; p += ABLK) {
            unsigned long long k = s_keys[p];
            int rank = 0;
            for (int j = 0; j < cnt4; j += 4) {
                rank += (s_keys[j + 0] > k) ? 1 : 0;
                rank += (s_keys[j + 1] > k) ? 1 : 0;
                rank += (s_keys[j + 2] > k) ? 1 : 0;
                rank += (s_keys[j + 3] > k) ? 1 : 0;
            }
            if (rank < KTOP) s_sel[rank] = k;
        }
    } else {
        // robust fallback: 20 rounds of full-row argmax (statistically never)
        unsigned long long bound = 0xFFFFFFFFFFFFFFFFull;
        const float* lrow = logits + (size_t)row * NV;
        for (int r = 0; r < KTOP; r++) {
            __syncthreads();
            if (tid == 0) s_win = 0ull;
            __syncthreads();
            unsigned long long loc = 0ull;
            for (int p = tid; p < NV; p += ABLK) {
                unsigned long long k = packkey(lrow[p], p);
                if (k < bound && k > loc) loc = k;
            }
            if (loc) atomicMax(&s_win, loc);
            __syncthreads();
            bound = s_win;
            if (tid == 0) s_sel[r] = s_win;
        }
    }
    __syncthreads();

    // ---- outputs: [sampled(NB) | topk_logprobs(NB*K) | topk_indices(NB*K)] ----
    if (tid < KTOP) {
        unsigned long long k = s_sel[tid];
        unsigned fb = (unsigned)(k >> 32);
        fb = (fb & 0x80000000u) ? (fb ^ 0x80000000u) : ~fb;
        float val = __uint_as_float(fb);
        int   idx = (int)(~(unsigned)(k & 0xFFFFFFFFull));
        out[NB + row * KTOP + tid]             = val * inv_t - s_lse;
        out[NB + NB * KTOP + row * KTOP + tid] = (float)idx;
    }
    if (tid == 0) {
        int gi = (int)(~(unsigned)(g_gkey[row] & 0xFFFFFFFFull));
        int i0 = (int)(~(unsigned)(s_sel[0] & 0xFFFFFFFFull));
        out[row] = (float)(greedy ? i0 : gi);
        // reset per-row state for the next graph replay
        g_cnt[row]  = 0;
        g_done[row] = 0;
        g_gkey[row] = 0ull;
    }
}

extern "C" void kernel_launch(void* const* d_in, const int* in_sizes, int n_in,
                              void* d_out, int out_size) {
    const float* logits = (const float*)d_in[0];
    const float* temp   = (const float*)d_in[1];
    const float* u      = (const float*)d_in[2];
    (void)in_sizes; (void)n_in; (void)out_size;
    sampler_kernel<<<NB * CHUNKS, ABLK>>>(logits, temp, u, (float*)d_out);
}